// round 7
// baseline (speedup 1.0000x reference)
#include <cuda_runtime.h>
#include <cuda_bf16.h>
#include <cstdint>

// ---------------------------------------------------------------------------
// FeatherNet via mma.sync bf16 HMMA. Split-bf16 3-pass (hi*hi + hi*lo + lo*hi)
// fp32 accumulate. 4-stage cp.async ring, K-chunk 16, wait_group 2.
// R7: R5 mainloop + post-barrier cp issue + pass2-interleaved A-lo reload.
// ---------------------------------------------------------------------------

using bf16 = __nv_bfloat16;

#define D_IN   2048
#define D_FF   8192
#define D_OUT  2048
#define BATCH  4096
#define SZN    5794
#define SZM    2897
#define SZN_PAD 5888            // 46*128
#define SZK_PAD 2944            // 184*16

#define OFF_B1 (D_FF * D_IN)                // 16777216
#define OFF_W2 (OFF_B1 + D_FF)              // 16785408
#define OFF_B2 (OFF_W2 + D_OUT * D_FF)      // 33562624

// ---------------- device scratch -------------------------------------------
__device__ bf16  g_V1hi[(size_t)SZN_PAD * SZK_PAD];
__device__ bf16  g_V1lo[(size_t)SZN_PAD * SZK_PAD];
__device__ bf16  g_V2hi[(size_t)SZN_PAD * SZK_PAD];
__device__ bf16  g_V2lo[(size_t)SZN_PAD * SZK_PAD];
__device__ bf16  g_Vhi[(size_t)SZN * SZN];
__device__ bf16  g_Vlo[(size_t)SZN * SZN];
__device__ bf16  g_xhi[(size_t)BATCH * D_IN];
__device__ bf16  g_xlo[(size_t)BATCH * D_IN];
__device__ bf16  g_hhi[(size_t)BATCH * D_FF];
__device__ bf16  g_hlo[(size_t)BATCH * D_FF];
__device__ float g_bias[D_FF + D_OUT];      // [b1 | b2]

// ---------------- PTX helpers ----------------------------------------------
__device__ __forceinline__ uint32_t smem_u32(const void* p) {
    uint32_t a;
    asm("{ .reg .u64 t; cvta.to.shared.u64 t, %1; cvt.u32.u64 %0, t; }"
        : "=r"(a) : "l"(p));
    return a;
}

#define CP16(sm, gp) \
    asm volatile("cp.async.cg.shared.global [%0], [%1], 16;" :: "r"(sm), "l"(gp))
#define CPCOMMIT() asm volatile("cp.async.commit_group;" ::: "memory")
#define CPWAIT2()  asm volatile("cp.async.wait_group 2;" ::: "memory")

#define LDSM4(r0, r1, r2, r3, addr) \
    asm volatile("ldmatrix.sync.aligned.m8n8.x4.shared.b16 {%0,%1,%2,%3}, [%4];" \
                 : "=r"(r0), "=r"(r1), "=r"(r2), "=r"(r3) : "r"(addr))

#define MMA(d, a, b0r, b1r) \
    asm volatile("mma.sync.aligned.m16n8k16.row.col.f32.bf16.bf16.f32 " \
                 "{%0,%1,%2,%3}, {%4,%5,%6,%7}, {%8,%9}, {%0,%1,%2,%3};" \
                 : "+f"((d)[0]), "+f"((d)[1]), "+f"((d)[2]), "+f"((d)[3]) \
                 : "r"((a)[0]), "r"((a)[1]), "r"((a)[2]), "r"((a)[3]), \
                   "r"(b0r), "r"(b1r))

// ---------------- tiling ---------------------------------------------------
#define ROWB      48
#define PLANE     (128 * ROWB)          // 6144 B
#define OFF_SA_HI 0
#define OFF_SA_LO PLANE
#define OFF_SB_HI (2 * PLANE)
#define OFF_SB_LO (3 * PLANE)
#define STAGE     (4 * PLANE)           // 24576 B
#define NSTAGE    4
#define SMEM_TOTAL (NSTAGE * STAGE)     // 98304 B

// ---------------------------------------------------------------------------
__global__ void split_pad(const float* __restrict__ src,
                          bf16* __restrict__ hi, bf16* __restrict__ lo,
                          int rows, int cols, int prows, int pcols)
{
    int idx = blockIdx.x * blockDim.x + threadIdx.x;
    int total = prows * pcols;
    if (idx >= total) return;
    int r = idx / pcols;
    int c = idx - r * pcols;
    float v = (r < rows && c < cols) ? src[(size_t)r * cols + c] : 0.0f;
    bf16 h = __float2bfloat16(v);
    hi[idx] = h;
    lo[idx] = __float2bfloat16(v - __bfloat162float(h));
}

// ---------------------------------------------------------------------------
// bias: out[j] = dot(V1[r,:], V2[c,:]) fp32, warp per output.
// ---------------------------------------------------------------------------
__global__ void bias_kernel(const float* __restrict__ V1, const float* __restrict__ V2,
                            float* __restrict__ biases)
{
    int w = (blockIdx.x * blockDim.x + threadIdx.x) >> 5;
    int lane = threadIdx.x & 31;
    if (w >= D_FF + D_OUT) return;
    size_t flat = (w < D_FF) ? ((size_t)OFF_B1 + w) : ((size_t)OFF_B2 + (w - D_FF));
    int r = (int)(flat / SZN);
    int c = (int)(flat - (size_t)r * SZN);
    const float* a = V1 + (size_t)r * SZM;
    const float* b = V2 + (size_t)c * SZM;
    float s = 0.0f;
    for (int k = lane; k < SZM; k += 32)
        s = fmaf(__ldg(a + k), __ldg(b + k), s);
    #pragma unroll
    for (int o = 16; o > 0; o >>= 1)
        s += __shfl_xor_sync(0xFFFFFFFFu, s, o);
    if (lane == 0) biases[w] = s;
}

// ---------------------------------------------------------------------------
// split-bf16 HMMA GEMM: C[M,N] = A @ B^T (+bias) (relu)
// ---------------------------------------------------------------------------
template<bool BIAS, bool RELU, bool STF32, bool HILO, bool BOUND>
__global__ __launch_bounds__(256, 1)
void gemm_mma(const bf16* __restrict__ Ahi, const bf16* __restrict__ Alo,
              const bf16* __restrict__ Bhi, const bf16* __restrict__ Blo,
              const float* __restrict__ bias,
              float* __restrict__ C, bf16* __restrict__ Chi, bf16* __restrict__ Clo,
              int M, int N, int K, int lda, int ldb, int ldc)
{
    extern __shared__ char smem[];
    const uint32_t sb = smem_u32(smem);
    const int tid  = threadIdx.x;
    const int lane = tid & 31, wid = tid >> 5;
    const int wm = wid >> 2;        // 0..1 : 64 rows
    const int wn = wid & 3;         // 0..3 : 32 cols
    const int brow = blockIdx.y * 128;
    const int bcol = blockIdx.x * 128;

    // cp.async geometry: thread -> (row, 16B chunk)
    const int lrow = tid >> 1, lch = tid & 1;
    const bf16* gAh = Ahi + (size_t)(brow + lrow) * lda + lch * 8;
    const bf16* gAl = Alo + (size_t)(brow + lrow) * lda + lch * 8;
    const bf16* gBh = Bhi + (size_t)(bcol + lrow) * ldb + lch * 8;
    const bf16* gBl = Blo + (size_t)(bcol + lrow) * ldb + lch * 8;
    const uint32_t stByte = (uint32_t)(lrow * ROWB + lch * 16);

    const uint32_t aByte = (uint32_t)((wm * 64 + (lane & 15)) * ROWB + (lane >> 4) * 16);
    const uint32_t bByte = (uint32_t)((wn * 32 + (lane & 15)) * ROWB + (lane >> 4) * 16);

    float acc[4][4][4];
    #pragma unroll
    for (int t = 0; t < 4; ++t)
        #pragma unroll
        for (int u = 0; u < 4; ++u)
            #pragma unroll
            for (int e = 0; e < 4; ++e) acc[t][u][e] = 0.0f;

    const int nk = K >> 4;

    auto issue = [&](int kb) {
        const uint32_t st = sb + (uint32_t)(kb & (NSTAGE - 1)) * STAGE + stByte;
        const size_t go = (size_t)kb * 16;
        CP16(st + OFF_SA_HI, gAh + go);
        CP16(st + OFF_SA_LO, gAl + go);
        CP16(st + OFF_SB_HI, gBh + go);
        CP16(st + OFF_SB_LO, gBl + go);
        CPCOMMIT();
    };

    issue(0); issue(1); issue(2);

    #pragma unroll 1
    for (int i = 0; i < nk; ++i) {
        CPWAIT2();
        __syncthreads();
        // stage (i+3)&3 == (i-1)&3 was fully consumed in epoch i-1 -> safe now
        if (i + 3 < nk) issue(i + 3);

        const uint32_t st = sb + (uint32_t)(i & (NSTAGE - 1)) * STAGE;

        uint32_t bh[8], bl[8], af[16];
        LDSM4(bh[0], bh[1], bh[2], bh[3], st + OFF_SB_HI + bByte);
        LDSM4(bh[4], bh[5], bh[6], bh[7], st + OFF_SB_HI + bByte + 16 * ROWB);
        LDSM4(bl[0], bl[1], bl[2], bl[3], st + OFF_SB_LO + bByte);
        LDSM4(bl[4], bl[5], bl[6], bl[7], st + OFF_SB_LO + bByte + 16 * ROWB);
        #pragma unroll
        for (int t = 0; t < 4; ++t)
            LDSM4(af[4*t], af[4*t+1], af[4*t+2], af[4*t+3],
                  st + OFF_SA_HI + aByte + (uint32_t)t * 16 * ROWB);

        // pass 1: Ahi * Bhi
        #pragma unroll
        for (int t = 0; t < 4; ++t)
            #pragma unroll
            for (int u = 0; u < 4; ++u) {
                const int p = u >> 1, q = u & 1;
                MMA(acc[t][u], &af[4*t], bh[4*p + q], bh[4*p + q + 2]);
            }
        // pass 2: Ahi * Blo, with A-lo reload interleaved right after the
        // last MMA that reads af[4t] (WAR only -> issue-ordered, no extra regs)
        #pragma unroll
        for (int t = 0; t < 4; ++t) {
            #pragma unroll
            for (int u = 0; u < 4; ++u) {
                const int p = u >> 1, q = u & 1;
                MMA(acc[t][u], &af[4*t], bl[4*p + q], bl[4*p + q + 2]);
            }
            LDSM4(af[4*t], af[4*t+1], af[4*t+2], af[4*t+3],
                  st + OFF_SA_LO + aByte + (uint32_t)t * 16 * ROWB);
        }
        // pass 3: Alo * Bhi
        #pragma unroll
        for (int t = 0; t < 4; ++t)
            #pragma unroll
            for (int u = 0; u < 4; ++u) {
                const int p = u >> 1, q = u & 1;
                MMA(acc[t][u], &af[4*t], bh[4*p + q], bh[4*p + q + 2]);
            }
    }

    // ---------------- epilogue (registers -> global, direct) ----------------
    const int l4  = lane >> 2;
    const int lc2 = (lane & 3) * 2;
    #pragma unroll
    for (int u = 0; u < 4; ++u) {
        const int col = bcol + wn * 32 + u * 8 + lc2;
        float b0 = 0.0f, b1 = 0.0f;
        if (BIAS) {
            b0 = __ldg(bias + col);
            b1 = __ldg(bias + col + 1);
        }
        #pragma unroll
        for (int t = 0; t < 4; ++t)
            #pragma unroll
            for (int h = 0; h < 2; ++h) {
                const int row = brow + wm * 64 + t * 16 + h * 8 + l4;
                // N even & col even -> pair [col, col+1] inside when col < N
                if (BOUND && (row >= M || col >= N)) continue;
                float v0 = acc[t][u][2*h + 0];
                float v1 = acc[t][u][2*h + 1];
                if (BIAS) { v0 += b0; v1 += b1; }
                if (RELU) { v0 = fmaxf(v0, 0.0f); v1 = fmaxf(v1, 0.0f); }
                const size_t o = (size_t)row * ldc + col;
                if (STF32) {
                    float2 f2; f2.x = v0; f2.y = v1;
                    *(float2*)(C + o) = f2;
                }
                if (HILO) {
                    __nv_bfloat162 hh = __floats2bfloat162_rn(v0, v1);
                    *(__nv_bfloat162*)(Chi + o) = hh;
                    __nv_bfloat162 ll = __floats2bfloat162_rn(
                        v0 - __bfloat162float(hh.x), v1 - __bfloat162float(hh.y));
                    *(__nv_bfloat162*)(Clo + o) = ll;
                }
            }
    }
}

// ---------------------------------------------------------------------------
// kernel_launch
// ---------------------------------------------------------------------------
extern "C" void kernel_launch(void* const* d_in, const int* in_sizes, int n_in,
                              void* d_out, int out_size)
{
    const float* x  = (const float*)d_in[0];   // [4096, 2048]
    const float* V1 = (const float*)d_in[1];   // [5794, 2897]
    const float* V2 = (const float*)d_in[2];   // [5794, 2897]
    float* out = (float*)d_out;                // [4096, 2048]

    bf16 *v1h, *v1l, *v2h, *v2l, *vh, *vl, *xh, *xl, *hh, *hl;
    float* gb;
    cudaGetSymbolAddress((void**)&v1h, g_V1hi);
    cudaGetSymbolAddress((void**)&v1l, g_V1lo);
    cudaGetSymbolAddress((void**)&v2h, g_V2hi);
    cudaGetSymbolAddress((void**)&v2l, g_V2lo);
    cudaGetSymbolAddress((void**)&vh,  g_Vhi);
    cudaGetSymbolAddress((void**)&vl,  g_Vlo);
    cudaGetSymbolAddress((void**)&xh,  g_xhi);
    cudaGetSymbolAddress((void**)&xl,  g_xlo);
    cudaGetSymbolAddress((void**)&hh,  g_hhi);
    cudaGetSymbolAddress((void**)&hl,  g_hlo);
    cudaGetSymbolAddress((void**)&gb,  g_bias);

    cudaFuncSetAttribute(gemm_mma<false, false, false, true,  true>,
                         cudaFuncAttributeMaxDynamicSharedMemorySize, SMEM_TOTAL);
    cudaFuncSetAttribute(gemm_mma<true,  true,  false, true,  false>,
                         cudaFuncAttributeMaxDynamicSharedMemorySize, SMEM_TOTAL);
    cudaFuncSetAttribute(gemm_mma<true,  false, true,  false, false>,
                         cudaFuncAttributeMaxDynamicSharedMemorySize, SMEM_TOTAL);

    // 1. split inputs into hi/lo planes; biases via fp32 dot products
    {
        int total = SZN_PAD * SZK_PAD;
        split_pad<<<(total + 255) / 256, 256>>>(V1, v1h, v1l, SZN, SZM, SZN_PAD, SZK_PAD);
        split_pad<<<(total + 255) / 256, 256>>>(V2, v2h, v2l, SZN, SZM, SZN_PAD, SZK_PAD);
        int totx = BATCH * D_IN;
        split_pad<<<(totx + 255) / 256, 256>>>(x, xh, xl, BATCH, D_IN, BATCH, D_IN);
        bias_kernel<<<(D_FF + D_OUT) / 8, 256>>>(V1, V2, gb);
    }

    // 2. V = V1 @ V2^T : hi/lo planes (bounded bf162 stores, ldc=5794 even)
    gemm_mma<false, false, false, true, true>
        <<<dim3(SZN_PAD / 128, SZN_PAD / 128), 256, SMEM_TOTAL>>>(
        v1h, v1l, v2h, v2l, nullptr,
        nullptr, vh, vl,
        SZN, SZN, SZK_PAD, SZK_PAD, SZK_PAD, SZN);

    // 3. h = relu(x @ W1^T + b1) : hi/lo planes
    gemm_mma<true, true, false, true, false>
        <<<dim3(D_FF / 128, BATCH / 128), 256, SMEM_TOTAL>>>(
        xh, xl, vh /*W1hi*/, vl /*W1lo*/, gb,
        nullptr, hh, hl,
        BATCH, D_FF, D_IN, D_IN, D_IN, D_FF);

    // 4. out = h @ W2^T + b2 : fp32
    gemm_mma<true, false, true, false, false>
        <<<dim3(D_OUT / 128, BATCH / 128), 256, SMEM_TOTAL>>>(
        hh, hl, vh + OFF_W2, vl + OFF_W2, gb + D_FF,
        out, nullptr, nullptr,
        BATCH, D_OUT, D_FF, D_FF, D_FF, D_OUT);
}

// round 8
// speedup vs baseline: 1.3204x; 1.3204x over previous
#include <cuda_runtime.h>
#include <cuda_bf16.h>
#include <cuda_fp16.h>
#include <cstdint>

// ---------------------------------------------------------------------------
// FeatherNet. GEMM1 (V=V1@V2^T): bf16 3-pass split, emits fp16 Vhi plane.
// GEMM2/3 (MLP): fp16 2-pass split — (Ahi+Alo)*Bhi — dropping A*Blo, whose
// magnitude equals B's fp16 rep error (~2.4e-4 rel). Biases via fp32 kernel.
// Mainloop = R5 structure (4-stage cp.async, K16, wait_group 2, issue at end).
// ---------------------------------------------------------------------------

using bf16 = __nv_bfloat16;
using u16  = uint16_t;

#define D_IN   2048
#define D_FF   8192
#define D_OUT  2048
#define BATCH  4096
#define SZN    5794
#define SZM    2897
#define SZN_PAD 5888            // 46*128
#define SZK_PAD 2944            // 184*16

#define OFF_B1 (D_FF * D_IN)                // 16777216
#define OFF_W2 (OFF_B1 + D_FF)              // 16785408
#define OFF_B2 (OFF_W2 + D_OUT * D_FF)      // 33562624

// ---------------- device scratch -------------------------------------------
__device__ bf16   g_V1hi[(size_t)SZN_PAD * SZK_PAD];
__device__ bf16   g_V1lo[(size_t)SZN_PAD * SZK_PAD];
__device__ bf16   g_V2hi[(size_t)SZN_PAD * SZK_PAD];
__device__ bf16   g_V2lo[(size_t)SZN_PAD * SZK_PAD];
__device__ __half g_Vh [(size_t)SZN * SZN];          // fp16 V (weights)
__device__ __half g_xh [(size_t)BATCH * D_IN];
__device__ __half g_xl [(size_t)BATCH * D_IN];
__device__ __half g_hh [(size_t)BATCH * D_FF];
__device__ __half g_hl [(size_t)BATCH * D_FF];
__device__ float  g_bias[D_FF + D_OUT];              // [b1 | b2]

// ---------------- PTX helpers ----------------------------------------------
__device__ __forceinline__ uint32_t smem_u32(const void* p) {
    uint32_t a;
    asm("{ .reg .u64 t; cvta.to.shared.u64 t, %1; cvt.u32.u64 %0, t; }"
        : "=r"(a) : "l"(p));
    return a;
}

#define CP16(sm, gp) \
    asm volatile("cp.async.cg.shared.global [%0], [%1], 16;" :: "r"(sm), "l"(gp))
#define CPCOMMIT() asm volatile("cp.async.commit_group;" ::: "memory")
#define CPWAIT2()  asm volatile("cp.async.wait_group 2;" ::: "memory")

#define LDSM4(r0, r1, r2, r3, addr) \
    asm volatile("ldmatrix.sync.aligned.m8n8.x4.shared.b16 {%0,%1,%2,%3}, [%4];" \
                 : "=r"(r0), "=r"(r1), "=r"(r2), "=r"(r3) : "r"(addr))

template<bool FP16>
__device__ __forceinline__ void mma16816(float* d, const uint32_t* a,
                                         uint32_t b0, uint32_t b1) {
    if constexpr (FP16)
        asm volatile("mma.sync.aligned.m16n8k16.row.col.f32.f16.f16.f32 "
                     "{%0,%1,%2,%3}, {%4,%5,%6,%7}, {%8,%9}, {%0,%1,%2,%3};"
                     : "+f"(d[0]), "+f"(d[1]), "+f"(d[2]), "+f"(d[3])
                     : "r"(a[0]), "r"(a[1]), "r"(a[2]), "r"(a[3]), "r"(b0), "r"(b1));
    else
        asm volatile("mma.sync.aligned.m16n8k16.row.col.f32.bf16.bf16.f32 "
                     "{%0,%1,%2,%3}, {%4,%5,%6,%7}, {%8,%9}, {%0,%1,%2,%3};"
                     : "+f"(d[0]), "+f"(d[1]), "+f"(d[2]), "+f"(d[3])
                     : "r"(a[0]), "r"(a[1]), "r"(a[2]), "r"(a[3]), "r"(b0), "r"(b1));
}

// ---------------- tiling ---------------------------------------------------
#define ROWB      48
#define PLANE     (128 * ROWB)          // 6144 B
#define NSTAGE    4
// plane offsets (per stage): A_HI=0, A_LO=PLANE, B_HI=2*PLANE, [B_LO=3*PLANE]
#define SMEM_3P   (NSTAGE * 4 * PLANE)  // 98304
#define SMEM_2P   (NSTAGE * 3 * PLANE)  // 73728

// ---------------------------------------------------------------------------
__global__ void split_pad_bf16(const float* __restrict__ src,
                               bf16* __restrict__ hi, bf16* __restrict__ lo,
                               int rows, int cols, int prows, int pcols)
{
    int idx = blockIdx.x * blockDim.x + threadIdx.x;
    int total = prows * pcols;
    if (idx >= total) return;
    int r = idx / pcols;
    int c = idx - r * pcols;
    float v = (r < rows && c < cols) ? src[(size_t)r * cols + c] : 0.0f;
    bf16 h = __float2bfloat16(v);
    hi[idx] = h;
    lo[idx] = __float2bfloat16(v - __bfloat162float(h));
}

__global__ void split_half(const float* __restrict__ src,
                           __half* __restrict__ hi, __half* __restrict__ lo, int n)
{
    int i = blockIdx.x * blockDim.x + threadIdx.x;
    if (i >= n) return;
    float v = src[i];
    __half h = __float2half_rn(v);
    hi[i] = h;
    lo[i] = __float2half_rn(v - __half2float(h));
}

// ---------------------------------------------------------------------------
// bias: out[j] = dot(V1[r,:], V2[c,:]) fp32, warp per output.
// ---------------------------------------------------------------------------
__global__ void bias_kernel(const float* __restrict__ V1, const float* __restrict__ V2,
                            float* __restrict__ biases)
{
    int w = (blockIdx.x * blockDim.x + threadIdx.x) >> 5;
    int lane = threadIdx.x & 31;
    if (w >= D_FF + D_OUT) return;
    size_t flat = (w < D_FF) ? ((size_t)OFF_B1 + w) : ((size_t)OFF_B2 + (w - D_FF));
    int r = (int)(flat / SZN);
    int c = (int)(flat - (size_t)r * SZN);
    const float* a = V1 + (size_t)r * SZM;
    const float* b = V2 + (size_t)c * SZM;
    float s = 0.0f;
    for (int k = lane; k < SZM; k += 32)
        s = fmaf(__ldg(a + k), __ldg(b + k), s);
    #pragma unroll
    for (int o = 16; o > 0; o >>= 1)
        s += __shfl_xor_sync(0xFFFFFFFFu, s, o);
    if (lane == 0) biases[w] = s;
}

// ---------------------------------------------------------------------------
// Split GEMM: C[M,N] = A @ B^T (+bias) (relu)
// NPASS==3 (bf16): Ahi*Bhi + Ahi*Blo + Alo*Bhi  (planes Ahi,Alo,Bhi,Blo)
// NPASS==2 (fp16): Ahi*Bhi + Alo*Bhi            (planes Ahi,Alo,Bhi)
// EMIT: 0 = fp32 C | 1 = fp16 Ch | 2 = fp16 Ch + Cl
// ---------------------------------------------------------------------------
template<int NPASS, bool FP16MMA, bool BIAS, bool RELU, int EMIT, bool BOUND>
__global__ __launch_bounds__(256, 1)
void gemm_mma(const u16* __restrict__ Ahi, const u16* __restrict__ Alo,
              const u16* __restrict__ Bhi, const u16* __restrict__ Blo,
              const float* __restrict__ bias,
              float* __restrict__ C, __half* __restrict__ Ch, __half* __restrict__ Cl,
              int M, int N, int K, int lda, int ldb, int ldc)
{
    constexpr int NPLANES = (NPASS == 3) ? 4 : 3;
    constexpr uint32_t STG = NPLANES * PLANE;
    constexpr uint32_t OA_HI = 0, OA_LO = PLANE, OB_HI = 2 * PLANE, OB_LO = 3 * PLANE;

    extern __shared__ char smem[];
    const uint32_t sb = smem_u32(smem);
    const int tid  = threadIdx.x;
    const int lane = tid & 31, wid = tid >> 5;
    const int wm = wid >> 2;        // 0..1 : 64 rows
    const int wn = wid & 3;         // 0..3 : 32 cols
    const int brow = blockIdx.y * 128;
    const int bcol = blockIdx.x * 128;

    // cp.async geometry: thread -> (row, 16B chunk)
    const int lrow = tid >> 1, lch = tid & 1;
    const u16* gAh = Ahi + (size_t)(brow + lrow) * lda + lch * 8;
    const u16* gAl = Alo + (size_t)(brow + lrow) * lda + lch * 8;
    const u16* gBh = Bhi + (size_t)(bcol + lrow) * ldb + lch * 8;
    const u16* gBl = (NPASS == 3) ? Blo + (size_t)(bcol + lrow) * ldb + lch * 8 : nullptr;
    const uint32_t stByte = (uint32_t)(lrow * ROWB + lch * 16);

    const uint32_t aByte = (uint32_t)((wm * 64 + (lane & 15)) * ROWB + (lane >> 4) * 16);
    const uint32_t bByte = (uint32_t)((wn * 32 + (lane & 15)) * ROWB + (lane >> 4) * 16);

    float acc[4][4][4];
    #pragma unroll
    for (int t = 0; t < 4; ++t)
        #pragma unroll
        for (int u = 0; u < 4; ++u)
            #pragma unroll
            for (int e = 0; e < 4; ++e) acc[t][u][e] = 0.0f;

    const int nk = K >> 4;

    auto issue = [&](int kb) {
        const uint32_t st = sb + (uint32_t)(kb & (NSTAGE - 1)) * STG + stByte;
        const size_t go = (size_t)kb * 16;
        CP16(st + OA_HI, gAh + go);
        CP16(st + OA_LO, gAl + go);
        CP16(st + OB_HI, gBh + go);
        if constexpr (NPASS == 3) CP16(st + OB_LO, gBl + go);
        CPCOMMIT();
    };

    issue(0); issue(1); issue(2);

    #pragma unroll 1
    for (int i = 0; i < nk; ++i) {
        CPWAIT2();
        __syncthreads();
        const uint32_t st = sb + (uint32_t)(i & (NSTAGE - 1)) * STG;

        if constexpr (NPASS == 3) {
            uint32_t bh[8], bl[8], af[16];
            LDSM4(bh[0], bh[1], bh[2], bh[3], st + OB_HI + bByte);
            LDSM4(bh[4], bh[5], bh[6], bh[7], st + OB_HI + bByte + 16 * ROWB);
            LDSM4(bl[0], bl[1], bl[2], bl[3], st + OB_LO + bByte);
            LDSM4(bl[4], bl[5], bl[6], bl[7], st + OB_LO + bByte + 16 * ROWB);
            #pragma unroll
            for (int t = 0; t < 4; ++t)
                LDSM4(af[4*t], af[4*t+1], af[4*t+2], af[4*t+3],
                      st + OA_HI + aByte + (uint32_t)t * 16 * ROWB);

            #pragma unroll
            for (int t = 0; t < 4; ++t)
                #pragma unroll
                for (int u = 0; u < 4; ++u) {
                    const int p = u >> 1, q = u & 1;
                    mma16816<FP16MMA>(acc[t][u], &af[4*t], bh[4*p + q], bh[4*p + q + 2]);
                }
            #pragma unroll
            for (int t = 0; t < 4; ++t)
                #pragma unroll
                for (int u = 0; u < 4; ++u) {
                    const int p = u >> 1, q = u & 1;
                    mma16816<FP16MMA>(acc[t][u], &af[4*t], bl[4*p + q], bl[4*p + q + 2]);
                }
            #pragma unroll
            for (int t = 0; t < 4; ++t)
                LDSM4(af[4*t], af[4*t+1], af[4*t+2], af[4*t+3],
                      st + OA_LO + aByte + (uint32_t)t * 16 * ROWB);
            #pragma unroll
            for (int t = 0; t < 4; ++t)
                #pragma unroll
                for (int u = 0; u < 4; ++u) {
                    const int p = u >> 1, q = u & 1;
                    mma16816<FP16MMA>(acc[t][u], &af[4*t], bh[4*p + q], bh[4*p + q + 2]);
                }
        } else {
            uint32_t bh[8], ah[16], al[16];
            LDSM4(bh[0], bh[1], bh[2], bh[3], st + OB_HI + bByte);
            LDSM4(bh[4], bh[5], bh[6], bh[7], st + OB_HI + bByte + 16 * ROWB);
            #pragma unroll
            for (int t = 0; t < 4; ++t)
                LDSM4(ah[4*t], ah[4*t+1], ah[4*t+2], ah[4*t+3],
                      st + OA_HI + aByte + (uint32_t)t * 16 * ROWB);
            #pragma unroll
            for (int t = 0; t < 4; ++t)
                LDSM4(al[4*t], al[4*t+1], al[4*t+2], al[4*t+3],
                      st + OA_LO + aByte + (uint32_t)t * 16 * ROWB);

            #pragma unroll
            for (int t = 0; t < 4; ++t)
                #pragma unroll
                for (int u = 0; u < 4; ++u) {
                    const int p = u >> 1, q = u & 1;
                    mma16816<FP16MMA>(acc[t][u], &ah[4*t], bh[4*p + q], bh[4*p + q + 2]);
                }
            #pragma unroll
            for (int t = 0; t < 4; ++t)
                #pragma unroll
                for (int u = 0; u < 4; ++u) {
                    const int p = u >> 1, q = u & 1;
                    mma16816<FP16MMA>(acc[t][u], &al[4*t], bh[4*p + q], bh[4*p + q + 2]);
                }
        }

        if (i + 3 < nk) issue(i + 3);   // R5-proven placement: end of body
    }

    // ---------------- epilogue (registers -> global, direct) ----------------
    const int l4  = lane >> 2;
    const int lc2 = (lane & 3) * 2;
    #pragma unroll
    for (int u = 0; u < 4; ++u) {
        const int col = bcol + wn * 32 + u * 8 + lc2;
        float b0 = 0.0f, b1 = 0.0f;
        if (BIAS) {
            b0 = __ldg(bias + col);
            b1 = __ldg(bias + col + 1);
        }
        #pragma unroll
        for (int t = 0; t < 4; ++t)
            #pragma unroll
            for (int h = 0; h < 2; ++h) {
                const int row = brow + wm * 64 + t * 16 + h * 8 + l4;
                // N even & col even -> pair [col, col+1] inside when col < N
                if (BOUND && (row >= M || col >= N)) continue;
                float v0 = acc[t][u][2*h + 0];
                float v1 = acc[t][u][2*h + 1];
                if (BIAS) { v0 += b0; v1 += b1; }
                if (RELU) { v0 = fmaxf(v0, 0.0f); v1 = fmaxf(v1, 0.0f); }
                const size_t o = (size_t)row * ldc + col;
                if (EMIT == 0) {
                    float2 f2; f2.x = v0; f2.y = v1;
                    *(float2*)(C + o) = f2;
                } else {
                    __half2 hh = __floats2half2_rn(v0, v1);
                    *(__half2*)(Ch + o) = hh;
                    if (EMIT == 2) {
                        __half2 ll = __floats2half2_rn(
                            v0 - __half2float(__low2half(hh)),
                            v1 - __half2float(__high2half(hh)));
                        *(__half2*)(Cl + o) = ll;
                    }
                }
            }
    }
}

// ---------------------------------------------------------------------------
// kernel_launch
// ---------------------------------------------------------------------------
extern "C" void kernel_launch(void* const* d_in, const int* in_sizes, int n_in,
                              void* d_out, int out_size)
{
    const float* x  = (const float*)d_in[0];   // [4096, 2048]
    const float* V1 = (const float*)d_in[1];   // [5794, 2897]
    const float* V2 = (const float*)d_in[2];   // [5794, 2897]
    float* out = (float*)d_out;                // [4096, 2048]

    bf16 *v1h, *v1l, *v2h, *v2l;
    __half *vh, *xh, *xl, *hh, *hl;
    float* gb;
    cudaGetSymbolAddress((void**)&v1h, g_V1hi);
    cudaGetSymbolAddress((void**)&v1l, g_V1lo);
    cudaGetSymbolAddress((void**)&v2h, g_V2hi);
    cudaGetSymbolAddress((void**)&v2l, g_V2lo);
    cudaGetSymbolAddress((void**)&vh,  g_Vh);
    cudaGetSymbolAddress((void**)&xh,  g_xh);
    cudaGetSymbolAddress((void**)&xl,  g_xl);
    cudaGetSymbolAddress((void**)&hh,  g_hh);
    cudaGetSymbolAddress((void**)&hl,  g_hl);
    cudaGetSymbolAddress((void**)&gb,  g_bias);

    auto k1 = gemm_mma<3, false, false, false, 1, true>;
    auto k2 = gemm_mma<2, true,  true,  true,  2, false>;
    auto k3 = gemm_mma<2, true,  true,  false, 0, false>;
    cudaFuncSetAttribute(k1, cudaFuncAttributeMaxDynamicSharedMemorySize, SMEM_3P);
    cudaFuncSetAttribute(k2, cudaFuncAttributeMaxDynamicSharedMemorySize, SMEM_2P);
    cudaFuncSetAttribute(k3, cudaFuncAttributeMaxDynamicSharedMemorySize, SMEM_2P);

    // 1. operand prep
    {
        int total = SZN_PAD * SZK_PAD;
        split_pad_bf16<<<(total + 255) / 256, 256>>>(V1, v1h, v1l, SZN, SZM, SZN_PAD, SZK_PAD);
        split_pad_bf16<<<(total + 255) / 256, 256>>>(V2, v2h, v2l, SZN, SZM, SZN_PAD, SZK_PAD);
        int totx = BATCH * D_IN;
        split_half<<<(totx + 255) / 256, 256>>>(x, xh, xl, totx);
        bias_kernel<<<(D_FF + D_OUT) / 8, 256>>>(V1, V2, gb);
    }

    // 2. V = V1 @ V2^T  (bf16 3-pass) -> fp16 Vh plane (ldc=5794, even)
    k1<<<dim3(SZN_PAD / 128, SZN_PAD / 128), 256, SMEM_3P>>>(
        (const u16*)v1h, (const u16*)v1l, (const u16*)v2h, (const u16*)v2l,
        nullptr, nullptr, vh, nullptr,
        SZN, SZN, SZK_PAD, SZK_PAD, SZK_PAD, SZN);

    // 3. h = relu((xhi+xlo) @ W1hi^T + b1)  (fp16 2-pass) -> fp16 hi/lo
    k2<<<dim3(D_FF / 128, BATCH / 128), 256, SMEM_2P>>>(
        (const u16*)xh, (const u16*)xl, (const u16*)vh, nullptr,
        gb, nullptr, hh, hl,
        BATCH, D_FF, D_IN, D_IN, D_IN, D_FF);

    // 4. out = (hhi+hlo) @ W2hi^T + b2  (fp16 2-pass) -> fp32
    k3<<<dim3(D_OUT / 128, BATCH / 128), 256, SMEM_2P>>>(
        (const u16*)hh, (const u16*)hl, (const u16*)(vh + OFF_W2), nullptr,
        gb + D_FF, out, nullptr, nullptr,
        BATCH, D_OUT, D_FF, D_FF, D_FF, D_OUT);
}

// round 9
// speedup vs baseline: 1.5416x; 1.1675x over previous
#include <cuda_runtime.h>
#include <cuda_bf16.h>
#include <cuda_fp16.h>
#include <cstdint>

// ---------------------------------------------------------------------------
// FeatherNet, all-fp16 2-pass split GEMMs: (Ahi+Alo)*Bhi, fp32 accumulate —
// dropped A*Blo term == B's fp16 rep error (~2.4e-4 rel).
// GEMM1 operands pre-scaled by 64 (lo parts stay fp16-normal); epilogue
// multiplies by 2^-12 before emitting the fp16 V plane. Biases via fp32 dots.
// Mainloop: 4-stage cp.async ring, K-chunk 16, wait_group 2, issue at end (R5).
// ---------------------------------------------------------------------------

using u16 = uint16_t;

#define D_IN   2048
#define D_FF   8192
#define D_OUT  2048
#define BATCH  4096
#define SZN    5794
#define SZM    2897
#define SZN_PAD 5888            // 46*128
#define SZK_PAD 2944            // 184*16

#define OFF_B1 (D_FF * D_IN)                // 16777216
#define OFF_W2 (OFF_B1 + D_FF)              // 16785408
#define OFF_B2 (OFF_W2 + D_OUT * D_FF)      // 33562624

#define V_SCALE     64.0f
#define V_DESCALE   (1.0f / 4096.0f)

// ---------------- device scratch -------------------------------------------
__device__ __half g_V1hi[(size_t)SZN_PAD * SZK_PAD];
__device__ __half g_V1lo[(size_t)SZN_PAD * SZK_PAD];
__device__ __half g_V2hi[(size_t)SZN_PAD * SZK_PAD];
__device__ __half g_Vh [(size_t)SZN * SZN];          // fp16 V (weights)
__device__ __half g_xh [(size_t)BATCH * D_IN];
__device__ __half g_xl [(size_t)BATCH * D_IN];
__device__ __half g_hh [(size_t)BATCH * D_FF];
__device__ __half g_hl [(size_t)BATCH * D_FF];
__device__ float  g_bias[D_FF + D_OUT];              // [b1 | b2]

// ---------------- PTX helpers ----------------------------------------------
__device__ __forceinline__ uint32_t smem_u32(const void* p) {
    uint32_t a;
    asm("{ .reg .u64 t; cvta.to.shared.u64 t, %1; cvt.u32.u64 %0, t; }"
        : "=r"(a) : "l"(p));
    return a;
}

#define CP16(sm, gp) \
    asm volatile("cp.async.cg.shared.global [%0], [%1], 16;" :: "r"(sm), "l"(gp))
#define CPCOMMIT() asm volatile("cp.async.commit_group;" ::: "memory")
#define CPWAIT2()  asm volatile("cp.async.wait_group 2;" ::: "memory")

#define LDSM4(r0, r1, r2, r3, addr) \
    asm volatile("ldmatrix.sync.aligned.m8n8.x4.shared.b16 {%0,%1,%2,%3}, [%4];" \
                 : "=r"(r0), "=r"(r1), "=r"(r2), "=r"(r3) : "r"(addr))

__device__ __forceinline__ void mma_f16(float* d, const uint32_t* a,
                                        uint32_t b0, uint32_t b1) {
    asm volatile("mma.sync.aligned.m16n8k16.row.col.f32.f16.f16.f32 "
                 "{%0,%1,%2,%3}, {%4,%5,%6,%7}, {%8,%9}, {%0,%1,%2,%3};"
                 : "+f"(d[0]), "+f"(d[1]), "+f"(d[2]), "+f"(d[3])
                 : "r"(a[0]), "r"(a[1]), "r"(a[2]), "r"(a[3]), "r"(b0), "r"(b1));
}

// ---------------- tiling ---------------------------------------------------
#define ROWB      48
#define PLANE     (128 * ROWB)          // 6144 B
#define NSTAGE    4
#define STG       (3 * PLANE)           // 18432 B per stage (A_HI, A_LO, B_HI)
#define OA_HI     0u
#define OA_LO     ((uint32_t)PLANE)
#define OB_HI     ((uint32_t)(2 * PLANE))
#define SMEM_2P   (NSTAGE * STG)        // 73728 B

// ---------------------------------------------------------------------------
// split/pad fp32 -> scaled fp16 hi/lo planes [prows, pcols], zero pad.
// WANT_LO=false skips the lo plane (for V2: only hi is consumed).
// ---------------------------------------------------------------------------
template<bool WANT_LO>
__global__ void split_half_pad(const float* __restrict__ src,
                               __half* __restrict__ hi, __half* __restrict__ lo,
                               int rows, int cols, int prows, int pcols, float scale)
{
    int idx = blockIdx.x * blockDim.x + threadIdx.x;
    int total = prows * pcols;
    if (idx >= total) return;
    int r = idx / pcols;
    int c = idx - r * pcols;
    float v = (r < rows && c < cols) ? src[(size_t)r * cols + c] * scale : 0.0f;
    __half h = __float2half_rn(v);
    hi[idx] = h;
    if (WANT_LO) lo[idx] = __float2half_rn(v - __half2float(h));
}

__global__ void split_half(const float* __restrict__ src,
                           __half* __restrict__ hi, __half* __restrict__ lo, int n)
{
    int i = blockIdx.x * blockDim.x + threadIdx.x;
    if (i >= n) return;
    float v = src[i];
    __half h = __float2half_rn(v);
    hi[i] = h;
    lo[i] = __float2half_rn(v - __half2float(h));
}

// ---------------------------------------------------------------------------
// bias: out[j] = dot(V1[r,:], V2[c,:]) fp32, warp per output.
// ---------------------------------------------------------------------------
__global__ void bias_kernel(const float* __restrict__ V1, const float* __restrict__ V2,
                            float* __restrict__ biases)
{
    int w = (blockIdx.x * blockDim.x + threadIdx.x) >> 5;
    int lane = threadIdx.x & 31;
    if (w >= D_FF + D_OUT) return;
    size_t flat = (w < D_FF) ? ((size_t)OFF_B1 + w) : ((size_t)OFF_B2 + (w - D_FF));
    int r = (int)(flat / SZN);
    int c = (int)(flat - (size_t)r * SZN);
    const float* a = V1 + (size_t)r * SZM;
    const float* b = V2 + (size_t)c * SZM;
    float s = 0.0f;
    for (int k = lane; k < SZM; k += 32)
        s = fmaf(__ldg(a + k), __ldg(b + k), s);
    #pragma unroll
    for (int o = 16; o > 0; o >>= 1)
        s += __shfl_xor_sync(0xFFFFFFFFu, s, o);
    if (lane == 0) biases[w] = s;
}

// ---------------------------------------------------------------------------
// fp16 2-pass split GEMM: C[M,N] = oscale * (A @ B^T) (+bias) (relu)
//   passes: Ahi*Bhi + Alo*Bhi
// EMIT: 0 = fp32 C | 1 = fp16 Ch | 2 = fp16 Ch + Cl
// ---------------------------------------------------------------------------
template<bool BIAS, bool RELU, int EMIT, bool BOUND>
__global__ __launch_bounds__(256, 1)
void gemm_mma(const u16* __restrict__ Ahi, const u16* __restrict__ Alo,
              const u16* __restrict__ Bhi,
              const float* __restrict__ bias,
              float* __restrict__ C, __half* __restrict__ Ch, __half* __restrict__ Cl,
              int M, int N, int K, int lda, int ldb, int ldc, float oscale)
{
    extern __shared__ char smem[];
    const uint32_t sb = smem_u32(smem);
    const int tid  = threadIdx.x;
    const int lane = tid & 31, wid = tid >> 5;
    const int wm = wid >> 2;        // 0..1 : 64 rows
    const int wn = wid & 3;         // 0..3 : 32 cols
    const int brow = blockIdx.y * 128;
    const int bcol = blockIdx.x * 128;

    // cp.async geometry: thread -> (row, 16B chunk)
    const int lrow = tid >> 1, lch = tid & 1;
    const u16* gAh = Ahi + (size_t)(brow + lrow) * lda + lch * 8;
    const u16* gAl = Alo + (size_t)(brow + lrow) * lda + lch * 8;
    const u16* gBh = Bhi + (size_t)(bcol + lrow) * ldb + lch * 8;
    const uint32_t stByte = (uint32_t)(lrow * ROWB + lch * 16);

    const uint32_t aByte = (uint32_t)((wm * 64 + (lane & 15)) * ROWB + (lane >> 4) * 16);
    const uint32_t bByte = (uint32_t)((wn * 32 + (lane & 15)) * ROWB + (lane >> 4) * 16);

    float acc[4][4][4];
    #pragma unroll
    for (int t = 0; t < 4; ++t)
        #pragma unroll
        for (int u = 0; u < 4; ++u)
            #pragma unroll
            for (int e = 0; e < 4; ++e) acc[t][u][e] = 0.0f;

    const int nk = K >> 4;

    auto issue = [&](int kb) {
        const uint32_t st = sb + (uint32_t)(kb & (NSTAGE - 1)) * STG + stByte;
        const size_t go = (size_t)kb * 16;
        CP16(st + OA_HI, gAh + go);
        CP16(st + OA_LO, gAl + go);
        CP16(st + OB_HI, gBh + go);
        CPCOMMIT();
    };

    issue(0); issue(1); issue(2);

    #pragma unroll 1
    for (int i = 0; i < nk; ++i) {
        CPWAIT2();
        __syncthreads();
        const uint32_t st = sb + (uint32_t)(i & (NSTAGE - 1)) * STG;

        uint32_t bh[8], ah[16], al[16];
        LDSM4(bh[0], bh[1], bh[2], bh[3], st + OB_HI + bByte);
        LDSM4(bh[4], bh[5], bh[6], bh[7], st + OB_HI + bByte + 16 * ROWB);
        #pragma unroll
        for (int t = 0; t < 4; ++t)
            LDSM4(ah[4*t], ah[4*t+1], ah[4*t+2], ah[4*t+3],
                  st + OA_HI + aByte + (uint32_t)t * 16 * ROWB);
        #pragma unroll
        for (int t = 0; t < 4; ++t)
            LDSM4(al[4*t], al[4*t+1], al[4*t+2], al[4*t+3],
                  st + OA_LO + aByte + (uint32_t)t * 16 * ROWB);

        // pass 1: Ahi * Bhi
        #pragma unroll
        for (int t = 0; t < 4; ++t)
            #pragma unroll
            for (int u = 0; u < 4; ++u) {
                const int p = u >> 1, q = u & 1;
                mma_f16(acc[t][u], &ah[4*t], bh[4*p + q], bh[4*p + q + 2]);
            }
        // pass 2: Alo * Bhi
        #pragma unroll
        for (int t = 0; t < 4; ++t)
            #pragma unroll
            for (int u = 0; u < 4; ++u) {
                const int p = u >> 1, q = u & 1;
                mma_f16(acc[t][u], &al[4*t], bh[4*p + q], bh[4*p + q + 2]);
            }

        if (i + 3 < nk) issue(i + 3);   // R5-proven placement
    }

    // ---------------- epilogue (registers -> global, direct) ----------------
    const int l4  = lane >> 2;
    const int lc2 = (lane & 3) * 2;
    #pragma unroll
    for (int u = 0; u < 4; ++u) {
        const int col = bcol + wn * 32 + u * 8 + lc2;
        float b0 = 0.0f, b1 = 0.0f;
        if (BIAS) {
            b0 = __ldg(bias + col);
            b1 = __ldg(bias + col + 1);
        }
        #pragma unroll
        for (int t = 0; t < 4; ++t)
            #pragma unroll
            for (int h = 0; h < 2; ++h) {
                const int row = brow + wm * 64 + t * 16 + h * 8 + l4;
                // N even & col even -> pair [col, col+1] inside when col < N
                if (BOUND && (row >= M || col >= N)) continue;
                float v0 = acc[t][u][2*h + 0] * oscale;
                float v1 = acc[t][u][2*h + 1] * oscale;
                if (BIAS) { v0 += b0; v1 += b1; }
                if (RELU) { v0 = fmaxf(v0, 0.0f); v1 = fmaxf(v1, 0.0f); }
                const size_t o = (size_t)row * ldc + col;
                if (EMIT == 0) {
                    float2 f2; f2.x = v0; f2.y = v1;
                    *(float2*)(C + o) = f2;
                } else {
                    __half2 hh = __floats2half2_rn(v0, v1);
                    *(__half2*)(Ch + o) = hh;
                    if (EMIT == 2) {
                        __half2 ll = __floats2half2_rn(
                            v0 - __half2float(__low2half(hh)),
                            v1 - __half2float(__high2half(hh)));
                        *(__half2*)(Cl + o) = ll;
                    }
                }
            }
    }
}

// ---------------------------------------------------------------------------
// kernel_launch
// ---------------------------------------------------------------------------
extern "C" void kernel_launch(void* const* d_in, const int* in_sizes, int n_in,
                              void* d_out, int out_size)
{
    const float* x  = (const float*)d_in[0];   // [4096, 2048]
    const float* V1 = (const float*)d_in[1];   // [5794, 2897]
    const float* V2 = (const float*)d_in[2];   // [5794, 2897]
    float* out = (float*)d_out;                // [4096, 2048]

    __half *v1h, *v1l, *v2h, *vh, *xh, *xl, *hh, *hl;
    float* gb;
    cudaGetSymbolAddress((void**)&v1h, g_V1hi);
    cudaGetSymbolAddress((void**)&v1l, g_V1lo);
    cudaGetSymbolAddress((void**)&v2h, g_V2hi);
    cudaGetSymbolAddress((void**)&vh,  g_Vh);
    cudaGetSymbolAddress((void**)&xh,  g_xh);
    cudaGetSymbolAddress((void**)&xl,  g_xl);
    cudaGetSymbolAddress((void**)&hh,  g_hh);
    cudaGetSymbolAddress((void**)&hl,  g_hl);
    cudaGetSymbolAddress((void**)&gb,  g_bias);

    auto k1 = gemm_mma<false, false, 1, true>;   // V = V1@V2^T (scaled), fp16 out
    auto k2 = gemm_mma<true,  true,  2, false>;  // h  (fp16 hi/lo out)
    auto k3 = gemm_mma<true,  false, 0, false>;  // out (fp32)
    cudaFuncSetAttribute(k1, cudaFuncAttributeMaxDynamicSharedMemorySize, SMEM_2P);
    cudaFuncSetAttribute(k2, cudaFuncAttributeMaxDynamicSharedMemorySize, SMEM_2P);
    cudaFuncSetAttribute(k3, cudaFuncAttributeMaxDynamicSharedMemorySize, SMEM_2P);

    // 1. operand prep
    {
        int total = SZN_PAD * SZK_PAD;
        split_half_pad<true><<<(total + 255) / 256, 256>>>(
            V1, v1h, v1l, SZN, SZM, SZN_PAD, SZK_PAD, V_SCALE);
        split_half_pad<false><<<(total + 255) / 256, 256>>>(
            V2, v2h, nullptr, SZN, SZM, SZN_PAD, SZK_PAD, V_SCALE);
        int totx = BATCH * D_IN;
        split_half<<<(totx + 255) / 256, 256>>>(x, xh, xl, totx);
        bias_kernel<<<(D_FF + D_OUT) / 8, 256>>>(V1, V2, gb);
    }

    // 2. V = V1 @ V2^T  (fp16 2-pass, x4096 scaled) -> fp16 Vh (descale 2^-12)
    k1<<<dim3(SZN_PAD / 128, SZN_PAD / 128), 256, SMEM_2P>>>(
        (const u16*)v1h, (const u16*)v1l, (const u16*)v2h,
        nullptr, nullptr, vh, nullptr,
        SZN, SZN, SZK_PAD, SZK_PAD, SZK_PAD, SZN, V_DESCALE);

    // 3. h = relu((xhi+xlo) @ W1hi^T + b1) -> fp16 hi/lo
    k2<<<dim3(D_FF / 128, BATCH / 128), 256, SMEM_2P>>>(
        (const u16*)xh, (const u16*)xl, (const u16*)vh,
        gb, nullptr, hh, hl,
        BATCH, D_FF, D_IN, D_IN, D_IN, D_FF, 1.0f);

    // 4. out = (hhi+hlo) @ W2hi^T + b2 -> fp32
    k3<<<dim3(D_OUT / 128, BATCH / 128), 256, SMEM_2P>>>(
        (const u16*)hh, (const u16*)hl, (const u16*)(vh + OFF_W2),
        gb + D_FF, out, nullptr, nullptr,
        BATCH, D_OUT, D_FF, D_FF, D_FF, D_OUT, 1.0f);
}

// round 10
// speedup vs baseline: 1.8939x; 1.2285x over previous
#include <cuda_runtime.h>
#include <cuda_bf16.h>
#include <cuda_fp16.h>
#include <cstdint>

// ---------------------------------------------------------------------------
// FeatherNet, fp16 split GEMMs with fp32 accumulate.
// GEMM1 (V=V1@V2^T): 1-pass  V1hi*V2hi   (x64-scaled operands, 2^-12 descale)
// GEMM2/3 (MLP):     2-pass  (Ahi+Alo)*Bhi
// Error model: each fp16-rounded operand adds ~1.4e-4 rms (incoherent over K).
// Biases from fp32 dot-product kernel. Mainloop: 4-stage cp.async ring,
// K-chunk 16, wait_group 2, issue at end (R5-proven).
// ---------------------------------------------------------------------------

using u16 = uint16_t;

#define D_IN   2048
#define D_FF   8192
#define D_OUT  2048
#define BATCH  4096
#define SZN    5794
#define SZM    2897
#define SZN_PAD 5888            // 46*128
#define SZK_PAD 2944            // 184*16

#define OFF_B1 (D_FF * D_IN)                // 16777216
#define OFF_W2 (OFF_B1 + D_FF)              // 16785408
#define OFF_B2 (OFF_W2 + D_OUT * D_FF)      // 33562624

#define V_SCALE     64.0f
#define V_DESCALE   (1.0f / 4096.0f)

// ---------------- device scratch -------------------------------------------
__device__ __half g_V1hi[(size_t)SZN_PAD * SZK_PAD];
__device__ __half g_V2hi[(size_t)SZN_PAD * SZK_PAD];
__device__ __half g_Vh [(size_t)SZN * SZN];          // fp16 V (weights)
__device__ __half g_xh [(size_t)BATCH * D_IN];
__device__ __half g_xl [(size_t)BATCH * D_IN];
__device__ __half g_hh [(size_t)BATCH * D_FF];
__device__ __half g_hl [(size_t)BATCH * D_FF];
__device__ float  g_bias[D_FF + D_OUT];              // [b1 | b2]

// ---------------- PTX helpers ----------------------------------------------
__device__ __forceinline__ uint32_t smem_u32(const void* p) {
    uint32_t a;
    asm("{ .reg .u64 t; cvta.to.shared.u64 t, %1; cvt.u32.u64 %0, t; }"
        : "=r"(a) : "l"(p));
    return a;
}

#define CP16(sm, gp) \
    asm volatile("cp.async.cg.shared.global [%0], [%1], 16;" :: "r"(sm), "l"(gp))
#define CPCOMMIT() asm volatile("cp.async.commit_group;" ::: "memory")
#define CPWAIT2()  asm volatile("cp.async.wait_group 2;" ::: "memory")

#define LDSM4(r0, r1, r2, r3, addr) \
    asm volatile("ldmatrix.sync.aligned.m8n8.x4.shared.b16 {%0,%1,%2,%3}, [%4];" \
                 : "=r"(r0), "=r"(r1), "=r"(r2), "=r"(r3) : "r"(addr))

__device__ __forceinline__ void mma_f16(float* d, const uint32_t* a,
                                        uint32_t b0, uint32_t b1) {
    asm volatile("mma.sync.aligned.m16n8k16.row.col.f32.f16.f16.f32 "
                 "{%0,%1,%2,%3}, {%4,%5,%6,%7}, {%8,%9}, {%0,%1,%2,%3};"
                 : "+f"(d[0]), "+f"(d[1]), "+f"(d[2]), "+f"(d[3])
                 : "r"(a[0]), "r"(a[1]), "r"(a[2]), "r"(a[3]), "r"(b0), "r"(b1));
}

// ---------------- tiling ---------------------------------------------------
#define ROWB      48
#define PLANE     (128 * ROWB)          // 6144 B
#define NSTAGE    4
// per-stage planes: A_HI [, A_LO], B_HI  -> STG = (NPASS+1)*PLANE
#define SMEM_1P   (NSTAGE * 2 * PLANE)  // 49152 B
#define SMEM_2P   (NSTAGE * 3 * PLANE)  // 73728 B

// ---------------------------------------------------------------------------
// split/pad fp32 -> scaled fp16 hi[/lo] planes [prows, pcols], zero pad.
// ---------------------------------------------------------------------------
template<bool WANT_LO>
__global__ void split_half_pad(const float* __restrict__ src,
                               __half* __restrict__ hi, __half* __restrict__ lo,
                               int rows, int cols, int prows, int pcols, float scale)
{
    int idx = blockIdx.x * blockDim.x + threadIdx.x;
    int total = prows * pcols;
    if (idx >= total) return;
    int r = idx / pcols;
    int c = idx - r * pcols;
    float v = (r < rows && c < cols) ? src[(size_t)r * cols + c] * scale : 0.0f;
    __half h = __float2half_rn(v);
    hi[idx] = h;
    if (WANT_LO) lo[idx] = __float2half_rn(v - __half2float(h));
}

__global__ void split_half(const float* __restrict__ src,
                           __half* __restrict__ hi, __half* __restrict__ lo, int n)
{
    int i = blockIdx.x * blockDim.x + threadIdx.x;
    if (i >= n) return;
    float v = src[i];
    __half h = __float2half_rn(v);
    hi[i] = h;
    lo[i] = __float2half_rn(v - __half2float(h));
}

// ---------------------------------------------------------------------------
// bias: out[j] = dot(V1[r,:], V2[c,:]) fp32, warp per output.
// ---------------------------------------------------------------------------
__global__ void bias_kernel(const float* __restrict__ V1, const float* __restrict__ V2,
                            float* __restrict__ biases)
{
    int w = (blockIdx.x * blockDim.x + threadIdx.x) >> 5;
    int lane = threadIdx.x & 31;
    if (w >= D_FF + D_OUT) return;
    size_t flat = (w < D_FF) ? ((size_t)OFF_B1 + w) : ((size_t)OFF_B2 + (w - D_FF));
    int r = (int)(flat / SZN);
    int c = (int)(flat - (size_t)r * SZN);
    const float* a = V1 + (size_t)r * SZM;
    const float* b = V2 + (size_t)c * SZM;
    float s = 0.0f;
    for (int k = lane; k < SZM; k += 32)
        s = fmaf(__ldg(a + k), __ldg(b + k), s);
    #pragma unroll
    for (int o = 16; o > 0; o >>= 1)
        s += __shfl_xor_sync(0xFFFFFFFFu, s, o);
    if (lane == 0) biases[w] = s;
}

// ---------------------------------------------------------------------------
// fp16 split GEMM: C[M,N] = oscale * (A @ B^T) (+bias) (relu)
// NPASS=1: Ahi*Bhi            NPASS=2: Ahi*Bhi + Alo*Bhi
// EMIT: 0 = fp32 C | 1 = fp16 Ch | 2 = fp16 Ch + Cl
// ---------------------------------------------------------------------------
template<int NPASS, bool BIAS, bool RELU, int EMIT, bool BOUND>
__global__ __launch_bounds__(256, 1)
void gemm_mma(const u16* __restrict__ Ahi, const u16* __restrict__ Alo,
              const u16* __restrict__ Bhi,
              const float* __restrict__ bias,
              float* __restrict__ C, __half* __restrict__ Ch, __half* __restrict__ Cl,
              int M, int N, int K, int lda, int ldb, int ldc, float oscale)
{
    constexpr uint32_t STG   = (NPASS + 1) * PLANE;
    constexpr uint32_t OA_HI = 0;
    constexpr uint32_t OA_LO = PLANE;                 // only when NPASS==2
    constexpr uint32_t OB_HI = NPASS * PLANE;

    extern __shared__ char smem[];
    const uint32_t sb = smem_u32(smem);
    const int tid  = threadIdx.x;
    const int lane = tid & 31, wid = tid >> 5;
    const int wm = wid >> 2;        // 0..1 : 64 rows
    const int wn = wid & 3;         // 0..3 : 32 cols
    const int brow = blockIdx.y * 128;
    const int bcol = blockIdx.x * 128;

    // cp.async geometry: thread -> (row, 16B chunk)
    const int lrow = tid >> 1, lch = tid & 1;
    const u16* gAh = Ahi + (size_t)(brow + lrow) * lda + lch * 8;
    const u16* gAl = (NPASS == 2) ? Alo + (size_t)(brow + lrow) * lda + lch * 8 : nullptr;
    const u16* gBh = Bhi + (size_t)(bcol + lrow) * ldb + lch * 8;
    const uint32_t stByte = (uint32_t)(lrow * ROWB + lch * 16);

    const uint32_t aByte = (uint32_t)((wm * 64 + (lane & 15)) * ROWB + (lane >> 4) * 16);
    const uint32_t bByte = (uint32_t)((wn * 32 + (lane & 15)) * ROWB + (lane >> 4) * 16);

    float acc[4][4][4];
    #pragma unroll
    for (int t = 0; t < 4; ++t)
        #pragma unroll
        for (int u = 0; u < 4; ++u)
            #pragma unroll
            for (int e = 0; e < 4; ++e) acc[t][u][e] = 0.0f;

    const int nk = K >> 4;

    auto issue = [&](int kb) {
        const uint32_t st = sb + (uint32_t)(kb & (NSTAGE - 1)) * STG + stByte;
        const size_t go = (size_t)kb * 16;
        CP16(st + OA_HI, gAh + go);
        if constexpr (NPASS == 2) CP16(st + OA_LO, gAl + go);
        CP16(st + OB_HI, gBh + go);
        CPCOMMIT();
    };

    issue(0); issue(1); issue(2);

    #pragma unroll 1
    for (int i = 0; i < nk; ++i) {
        CPWAIT2();
        __syncthreads();
        const uint32_t st = sb + (uint32_t)(i & (NSTAGE - 1)) * STG;

        uint32_t bh[8], ah[16];
        LDSM4(bh[0], bh[1], bh[2], bh[3], st + OB_HI + bByte);
        LDSM4(bh[4], bh[5], bh[6], bh[7], st + OB_HI + bByte + 16 * ROWB);
        #pragma unroll
        for (int t = 0; t < 4; ++t)
            LDSM4(ah[4*t], ah[4*t+1], ah[4*t+2], ah[4*t+3],
                  st + OA_HI + aByte + (uint32_t)t * 16 * ROWB);

        // pass 1: Ahi * Bhi
        #pragma unroll
        for (int t = 0; t < 4; ++t)
            #pragma unroll
            for (int u = 0; u < 4; ++u) {
                const int p = u >> 1, q = u & 1;
                mma_f16(acc[t][u], &ah[4*t], bh[4*p + q], bh[4*p + q + 2]);
            }

        if constexpr (NPASS == 2) {
            uint32_t al[16];
            #pragma unroll
            for (int t = 0; t < 4; ++t)
                LDSM4(al[4*t], al[4*t+1], al[4*t+2], al[4*t+3],
                      st + OA_LO + aByte + (uint32_t)t * 16 * ROWB);
            #pragma unroll
            for (int t = 0; t < 4; ++t)
                #pragma unroll
                for (int u = 0; u < 4; ++u) {
                    const int p = u >> 1, q = u & 1;
                    mma_f16(acc[t][u], &al[4*t], bh[4*p + q], bh[4*p + q + 2]);
                }
        }

        if (i + 3 < nk) issue(i + 3);   // R5-proven placement
    }

    // ---------------- epilogue (registers -> global, direct) ----------------
    const int l4  = lane >> 2;
    const int lc2 = (lane & 3) * 2;
    #pragma unroll
    for (int u = 0; u < 4; ++u) {
        const int col = bcol + wn * 32 + u * 8 + lc2;
        float b0 = 0.0f, b1 = 0.0f;
        if (BIAS) {
            b0 = __ldg(bias + col);
            b1 = __ldg(bias + col + 1);
        }
        #pragma unroll
        for (int t = 0; t < 4; ++t)
            #pragma unroll
            for (int h = 0; h < 2; ++h) {
                const int row = brow + wm * 64 + t * 16 + h * 8 + l4;
                // N even & col even -> pair [col, col+1] inside when col < N
                if (BOUND && (row >= M || col >= N)) continue;
                float v0 = acc[t][u][2*h + 0] * oscale;
                float v1 = acc[t][u][2*h + 1] * oscale;
                if (BIAS) { v0 += b0; v1 += b1; }
                if (RELU) { v0 = fmaxf(v0, 0.0f); v1 = fmaxf(v1, 0.0f); }
                const size_t o = (size_t)row * ldc + col;
                if (EMIT == 0) {
                    float2 f2; f2.x = v0; f2.y = v1;
                    *(float2*)(C + o) = f2;
                } else {
                    __half2 hh = __floats2half2_rn(v0, v1);
                    *(__half2*)(Ch + o) = hh;
                    if (EMIT == 2) {
                        __half2 ll = __floats2half2_rn(
                            v0 - __half2float(__low2half(hh)),
                            v1 - __half2float(__high2half(hh)));
                        *(__half2*)(Cl + o) = ll;
                    }
                }
            }
    }
}

// ---------------------------------------------------------------------------
// kernel_launch
// ---------------------------------------------------------------------------
extern "C" void kernel_launch(void* const* d_in, const int* in_sizes, int n_in,
                              void* d_out, int out_size)
{
    const float* x  = (const float*)d_in[0];   // [4096, 2048]
    const float* V1 = (const float*)d_in[1];   // [5794, 2897]
    const float* V2 = (const float*)d_in[2];   // [5794, 2897]
    float* out = (float*)d_out;                // [4096, 2048]

    __half *v1h, *v2h, *vh, *xh, *xl, *hh, *hl;
    float* gb;
    cudaGetSymbolAddress((void**)&v1h, g_V1hi);
    cudaGetSymbolAddress((void**)&v2h, g_V2hi);
    cudaGetSymbolAddress((void**)&vh,  g_Vh);
    cudaGetSymbolAddress((void**)&xh,  g_xh);
    cudaGetSymbolAddress((void**)&xl,  g_xl);
    cudaGetSymbolAddress((void**)&hh,  g_hh);
    cudaGetSymbolAddress((void**)&hl,  g_hl);
    cudaGetSymbolAddress((void**)&gb,  g_bias);

    auto k1 = gemm_mma<1, false, false, 1, true>;   // V (1-pass, fp16 out)
    auto k2 = gemm_mma<2, true,  true,  2, false>;  // h  (fp16 hi/lo out)
    auto k3 = gemm_mma<2, true,  false, 0, false>;  // out (fp32)
    cudaFuncSetAttribute(k1, cudaFuncAttributeMaxDynamicSharedMemorySize, SMEM_1P);
    cudaFuncSetAttribute(k2, cudaFuncAttributeMaxDynamicSharedMemorySize, SMEM_2P);
    cudaFuncSetAttribute(k3, cudaFuncAttributeMaxDynamicSharedMemorySize, SMEM_2P);

    // 1. operand prep
    {
        int total = SZN_PAD * SZK_PAD;
        split_half_pad<false><<<(total + 255) / 256, 256>>>(
            V1, v1h, nullptr, SZN, SZM, SZN_PAD, SZK_PAD, V_SCALE);
        split_half_pad<false><<<(total + 255) / 256, 256>>>(
            V2, v2h, nullptr, SZN, SZM, SZN_PAD, SZK_PAD, V_SCALE);
        int totx = BATCH * D_IN;
        split_half<<<(totx + 255) / 256, 256>>>(x, xh, xl, totx);
        bias_kernel<<<(D_FF + D_OUT) / 8, 256>>>(V1, V2, gb);
    }

    // 2. V = V1hi @ V2hi^T  (1-pass, x4096 scaled) -> fp16 Vh (descale 2^-12)
    k1<<<dim3(SZN_PAD / 128, SZN_PAD / 128), 256, SMEM_1P>>>(
        (const u16*)v1h, nullptr, (const u16*)v2h,
        nullptr, nullptr, vh, nullptr,
        SZN, SZN, SZK_PAD, SZK_PAD, SZK_PAD, SZN, V_DESCALE);

    // 3. h = relu((xhi+xlo) @ W1hi^T + b1) -> fp16 hi/lo
    k2<<<dim3(D_FF / 128, BATCH / 128), 256, SMEM_2P>>>(
        (const u16*)xh, (const u16*)xl, (const u16*)vh,
        gb, nullptr, hh, hl,
        BATCH, D_FF, D_IN, D_IN, D_IN, D_FF, 1.0f);

    // 4. out = (hhi+hlo) @ W2hi^T + b2 -> fp32
    k3<<<dim3(D_OUT / 128, BATCH / 128), 256, SMEM_2P>>>(
        (const u16*)hh, (const u16*)hl, (const u16*)(vh + OFF_W2),
        gb + D_FF, out, nullptr, nullptr,
        BATCH, D_OUT, D_FF, D_FF, D_FF, D_OUT, 1.0f);
}

// round 11
// speedup vs baseline: 3.0282x; 1.5989x over previous
#include <cuda_runtime.h>
#include <cuda_bf16.h>
#include <cuda_fp16.h>
#include <cstdint>

// ---------------------------------------------------------------------------
// FeatherNet, all GEMMs 1-pass fp16 HMMA with fp32 accumulate.
//   V   = V1h @ V2h^T        (x64-scaled operands, 2^-12 descale, fp16 out)
//   h   = relu(xh @ W1h^T + b1)   (fp16 out)
//   out = hh @ W2h^T + b2         (fp32 out)
// Error budget (calibrated over R8-R10): each fp16-rounded operand adds
// ~2.4-2.9e-4 in quadrature -> predicted ~6.5e-4 < 1e-3.
// Biases from fp32 dot-product kernel (exact path for the additive terms).
// Mainloop: 5-stage cp.async ring, K-chunk 16, wait_group 3, issue at end.
// ---------------------------------------------------------------------------

using u16 = uint16_t;

#define D_IN   2048
#define D_FF   8192
#define D_OUT  2048
#define BATCH  4096
#define SZN    5794
#define SZM    2897
#define SZN_PAD 5888            // 46*128
#define SZK_PAD 2944            // 184*16

#define OFF_B1 (D_FF * D_IN)                // 16777216
#define OFF_W2 (OFF_B1 + D_FF)              // 16785408
#define OFF_B2 (OFF_W2 + D_OUT * D_FF)      // 33562624

#define V_SCALE     64.0f
#define V_DESCALE   (1.0f / 4096.0f)

// ---------------- device scratch -------------------------------------------
__device__ __half g_V1hi[(size_t)SZN_PAD * SZK_PAD];
__device__ __half g_V2hi[(size_t)SZN_PAD * SZK_PAD];
__device__ __half g_Vh [(size_t)SZN * SZN];          // fp16 V (weights)
__device__ __half g_xh [(size_t)BATCH * D_IN];
__device__ __half g_hh [(size_t)BATCH * D_FF];
__device__ float  g_bias[D_FF + D_OUT];              // [b1 | b2]

// ---------------- PTX helpers ----------------------------------------------
__device__ __forceinline__ uint32_t smem_u32(const void* p) {
    uint32_t a;
    asm("{ .reg .u64 t; cvta.to.shared.u64 t, %1; cvt.u32.u64 %0, t; }"
        : "=r"(a) : "l"(p));
    return a;
}

#define CP16(sm, gp) \
    asm volatile("cp.async.cg.shared.global [%0], [%1], 16;" :: "r"(sm), "l"(gp))
#define CPCOMMIT() asm volatile("cp.async.commit_group;" ::: "memory")
#define CPWAIT3()  asm volatile("cp.async.wait_group 3;" ::: "memory")

#define LDSM4(r0, r1, r2, r3, addr) \
    asm volatile("ldmatrix.sync.aligned.m8n8.x4.shared.b16 {%0,%1,%2,%3}, [%4];" \
                 : "=r"(r0), "=r"(r1), "=r"(r2), "=r"(r3) : "r"(addr))

__device__ __forceinline__ void mma_f16(float* d, const uint32_t* a,
                                        uint32_t b0, uint32_t b1) {
    asm volatile("mma.sync.aligned.m16n8k16.row.col.f32.f16.f16.f32 "
                 "{%0,%1,%2,%3}, {%4,%5,%6,%7}, {%8,%9}, {%0,%1,%2,%3};"
                 : "+f"(d[0]), "+f"(d[1]), "+f"(d[2]), "+f"(d[3])
                 : "r"(a[0]), "r"(a[1]), "r"(a[2]), "r"(a[3]), "r"(b0), "r"(b1));
}

// ---------------- tiling ---------------------------------------------------
#define ROWB      48
#define PLANE     (128 * ROWB)          // 6144 B
#define NSTAGE    5
#define STG       (2 * PLANE)           // 12288 B per stage (A_HI, B_HI)
#define OA_HI     0u
#define OB_HI     ((uint32_t)PLANE)
#define SMEM_1P   (NSTAGE * STG)        // 61440 B

// ---------------------------------------------------------------------------
// fp32 -> scaled fp16 plane [prows, pcols], zero pad.
// ---------------------------------------------------------------------------
__global__ void tohalf_pad(const float* __restrict__ src, __half* __restrict__ hi,
                           int rows, int cols, int prows, int pcols, float scale)
{
    int idx = blockIdx.x * blockDim.x + threadIdx.x;
    int total = prows * pcols;
    if (idx >= total) return;
    int r = idx / pcols;
    int c = idx - r * pcols;
    float v = (r < rows && c < cols) ? src[(size_t)r * cols + c] * scale : 0.0f;
    hi[idx] = __float2half_rn(v);
}

__global__ void tohalf(const float* __restrict__ src, __half* __restrict__ hi, int n)
{
    int i = blockIdx.x * blockDim.x + threadIdx.x;
    if (i >= n) return;
    hi[i] = __float2half_rn(src[i]);
}

// ---------------------------------------------------------------------------
// bias: out[j] = dot(V1[r,:], V2[c,:]) fp32, warp per output.
// ---------------------------------------------------------------------------
__global__ void bias_kernel(const float* __restrict__ V1, const float* __restrict__ V2,
                            float* __restrict__ biases)
{
    int w = (blockIdx.x * blockDim.x + threadIdx.x) >> 5;
    int lane = threadIdx.x & 31;
    if (w >= D_FF + D_OUT) return;
    size_t flat = (w < D_FF) ? ((size_t)OFF_B1 + w) : ((size_t)OFF_B2 + (w - D_FF));
    int r = (int)(flat / SZN);
    int c = (int)(flat - (size_t)r * SZN);
    const float* a = V1 + (size_t)r * SZM;
    const float* b = V2 + (size_t)c * SZM;
    float s = 0.0f;
    for (int k = lane; k < SZM; k += 32)
        s = fmaf(__ldg(a + k), __ldg(b + k), s);
    #pragma unroll
    for (int o = 16; o > 0; o >>= 1)
        s += __shfl_xor_sync(0xFFFFFFFFu, s, o);
    if (lane == 0) biases[w] = s;
}

// ---------------------------------------------------------------------------
// fp16 1-pass GEMM: C[M,N] = oscale * (A @ B^T) (+bias) (relu)
// EMIT: 0 = fp32 C | 1 = fp16 Ch
// ---------------------------------------------------------------------------
template<bool BIAS, bool RELU, int EMIT, bool BOUND>
__global__ __launch_bounds__(256, 1)
void gemm_mma(const u16* __restrict__ Ahi, const u16* __restrict__ Bhi,
              const float* __restrict__ bias,
              float* __restrict__ C, __half* __restrict__ Ch,
              int M, int N, int K, int lda, int ldb, int ldc, float oscale)
{
    extern __shared__ char smem[];
    const uint32_t sb = smem_u32(smem);
    const int tid  = threadIdx.x;
    const int lane = tid & 31, wid = tid >> 5;
    const int wm = wid >> 2;        // 0..1 : 64 rows
    const int wn = wid & 3;         // 0..3 : 32 cols
    const int brow = blockIdx.y * 128;
    const int bcol = blockIdx.x * 128;

    // cp.async geometry: thread -> (row, 16B chunk)
    const int lrow = tid >> 1, lch = tid & 1;
    const u16* gAh = Ahi + (size_t)(brow + lrow) * lda + lch * 8;
    const u16* gBh = Bhi + (size_t)(bcol + lrow) * ldb + lch * 8;
    const uint32_t stByte = (uint32_t)(lrow * ROWB + lch * 16);

    const uint32_t aByte = (uint32_t)((wm * 64 + (lane & 15)) * ROWB + (lane >> 4) * 16);
    const uint32_t bByte = (uint32_t)((wn * 32 + (lane & 15)) * ROWB + (lane >> 4) * 16);

    float acc[4][4][4];
    #pragma unroll
    for (int t = 0; t < 4; ++t)
        #pragma unroll
        for (int u = 0; u < 4; ++u)
            #pragma unroll
            for (int e = 0; e < 4; ++e) acc[t][u][e] = 0.0f;

    const int nk = K >> 4;

    auto issue = [&](int kb) {
        const uint32_t st = sb + (uint32_t)(kb % NSTAGE) * STG + stByte;
        const size_t go = (size_t)kb * 16;
        CP16(st + OA_HI, gAh + go);
        CP16(st + OB_HI, gBh + go);
        CPCOMMIT();
    };

    issue(0); issue(1); issue(2); issue(3);

    #pragma unroll 1
    for (int i = 0; i < nk; ++i) {
        CPWAIT3();
        __syncthreads();
        const uint32_t st = sb + (uint32_t)(i % NSTAGE) * STG;

        uint32_t bh[8], ah[16];
        LDSM4(bh[0], bh[1], bh[2], bh[3], st + OB_HI + bByte);
        LDSM4(bh[4], bh[5], bh[6], bh[7], st + OB_HI + bByte + 16 * ROWB);
        #pragma unroll
        for (int t = 0; t < 4; ++t)
            LDSM4(ah[4*t], ah[4*t+1], ah[4*t+2], ah[4*t+3],
                  st + OA_HI + aByte + (uint32_t)t * 16 * ROWB);

        #pragma unroll
        for (int t = 0; t < 4; ++t)
            #pragma unroll
            for (int u = 0; u < 4; ++u) {
                const int p = u >> 1, q = u & 1;
                mma_f16(acc[t][u], &ah[4*t], bh[4*p + q], bh[4*p + q + 2]);
            }

        if (i + 4 < nk) issue(i + 4);   // issue-at-end (R5-proven placement)
    }

    // ---------------- epilogue (registers -> global, direct) ----------------
    const int l4  = lane >> 2;
    const int lc2 = (lane & 3) * 2;
    #pragma unroll
    for (int u = 0; u < 4; ++u) {
        const int col = bcol + wn * 32 + u * 8 + lc2;
        float b0 = 0.0f, b1 = 0.0f;
        if (BIAS) {
            b0 = __ldg(bias + col);
            b1 = __ldg(bias + col + 1);
        }
        #pragma unroll
        for (int t = 0; t < 4; ++t)
            #pragma unroll
            for (int h = 0; h < 2; ++h) {
                const int row = brow + wm * 64 + t * 16 + h * 8 + l4;
                // N even & col even -> pair [col, col+1] inside when col < N
                if (BOUND && (row >= M || col >= N)) continue;
                float v0 = acc[t][u][2*h + 0] * oscale;
                float v1 = acc[t][u][2*h + 1] * oscale;
                if (BIAS) { v0 += b0; v1 += b1; }
                if (RELU) { v0 = fmaxf(v0, 0.0f); v1 = fmaxf(v1, 0.0f); }
                const size_t o = (size_t)row * ldc + col;
                if (EMIT == 0) {
                    float2 f2; f2.x = v0; f2.y = v1;
                    *(float2*)(C + o) = f2;
                } else {
                    *(__half2*)(Ch + o) = __floats2half2_rn(v0, v1);
                }
            }
    }
}

// ---------------------------------------------------------------------------
// kernel_launch
// ---------------------------------------------------------------------------
extern "C" void kernel_launch(void* const* d_in, const int* in_sizes, int n_in,
                              void* d_out, int out_size)
{
    const float* x  = (const float*)d_in[0];   // [4096, 2048]
    const float* V1 = (const float*)d_in[1];   // [5794, 2897]
    const float* V2 = (const float*)d_in[2];   // [5794, 2897]
    float* out = (float*)d_out;                // [4096, 2048]

    __half *v1h, *v2h, *vh, *xh, *hh;
    float* gb;
    cudaGetSymbolAddress((void**)&v1h, g_V1hi);
    cudaGetSymbolAddress((void**)&v2h, g_V2hi);
    cudaGetSymbolAddress((void**)&vh,  g_Vh);
    cudaGetSymbolAddress((void**)&xh,  g_xh);
    cudaGetSymbolAddress((void**)&hh,  g_hh);
    cudaGetSymbolAddress((void**)&gb,  g_bias);

    auto k1 = gemm_mma<false, false, 1, true>;   // V  (fp16 out, bounded)
    auto k2 = gemm_mma<true,  true,  1, false>;  // h  (fp16 out)
    auto k3 = gemm_mma<true,  false, 0, false>;  // out (fp32)
    cudaFuncSetAttribute(k1, cudaFuncAttributeMaxDynamicSharedMemorySize, SMEM_1P);
    cudaFuncSetAttribute(k2, cudaFuncAttributeMaxDynamicSharedMemorySize, SMEM_1P);
    cudaFuncSetAttribute(k3, cudaFuncAttributeMaxDynamicSharedMemorySize, SMEM_1P);

    // 1. operand prep
    {
        int total = SZN_PAD * SZK_PAD;
        tohalf_pad<<<(total + 255) / 256, 256>>>(
            V1, v1h, SZN, SZM, SZN_PAD, SZK_PAD, V_SCALE);
        tohalf_pad<<<(total + 255) / 256, 256>>>(
            V2, v2h, SZN, SZM, SZN_PAD, SZK_PAD, V_SCALE);
        int totx = BATCH * D_IN;
        tohalf<<<(totx + 255) / 256, 256>>>(x, xh, totx);
        bias_kernel<<<(D_FF + D_OUT) / 8, 256>>>(V1, V2, gb);
    }

    // 2. V = V1h @ V2h^T  (x4096 scaled) -> fp16 Vh (descale 2^-12)
    k1<<<dim3(SZN_PAD / 128, SZN_PAD / 128), 256, SMEM_1P>>>(
        (const u16*)v1h, (const u16*)v2h,
        nullptr, nullptr, vh,
        SZN, SZN, SZK_PAD, SZK_PAD, SZK_PAD, SZN, V_DESCALE);

    // 3. h = relu(xh @ W1h^T + b1) -> fp16
    k2<<<dim3(D_FF / 128, BATCH / 128), 256, SMEM_1P>>>(
        (const u16*)xh, (const u16*)vh,
        gb, nullptr, hh,
        BATCH, D_FF, D_IN, D_IN, D_IN, D_FF, 1.0f);

    // 4. out = hh @ W2h^T + b2 -> fp32
    k3<<<dim3(D_OUT / 128, BATCH / 128), 256, SMEM_1P>>>(
        (const u16*)hh, (const u16*)(vh + OFF_W2),
        gb + D_FF, out, nullptr,
        BATCH, D_OUT, D_FF, D_FF, D_FF, D_OUT, 1.0f);
}